// round 9
// baseline (speedup 1.0000x reference)
#include <cuda_runtime.h>
#include <math.h>
#include <stdint.h>

// Problem constants
#define DIMC   128
#define NWIN   49
#define HEADS  4
#define HD     32
#define NB     4096
#define M_TOTAL (NB * NWIN)        // 200704 = 1568 * 128

// Scratch (allocation-free rule: static device globals)
__device__ float g_qkv[(size_t)NB * NWIN * 384];   // [M, 384] : q|k|v per row
__device__ float g_comb[4 * 64 * 49 * 56];         // bias+mask, [h][wm][i][j(pad56)]

__device__ __forceinline__ float to_tf32(float x) {
    float r;
    asm("cvt.rna.tf32.f32 %0, %1;" : "=f"(r) : "f"(x));
    return r;
}
// round-to-nearest tf32 as raw bits (tensor core truncates low 13 bits)
__device__ __forceinline__ uint32_t rna_bits(float x) {
    return __float_as_uint(x) + 0x1000u;
}

__device__ __forceinline__ void mma_tf32(float c[4], const uint32_t a[4],
                                         uint32_t b0, uint32_t b1) {
    asm volatile(
        "mma.sync.aligned.m16n8k8.row.col.f32.tf32.tf32.f32 "
        "{%0,%1,%2,%3}, {%4,%5,%6,%7}, {%8,%9}, {%0,%1,%2,%3};"
        : "+f"(c[0]), "+f"(c[1]), "+f"(c[2]), "+f"(c[3])
        : "r"(a[0]), "r"(a[1]), "r"(a[2]), "r"(a[3]), "r"(b0), "r"(b1));
}

#define CP_ASYNC16(dst, src) \
    asm volatile("cp.async.ca.shared.global [%0], [%1], 16;" :: "r"(dst), "l"(src))
#define CP_COMMIT() asm volatile("cp.async.commit_group;")

// ---------------------------------------------------------------------------
// tf32 GEMM v3 (frozen round-5 winner): C[M][NC] = A[M][128]*W[NC][128]^T + b
// ---------------------------------------------------------------------------
#define GEMM_SMEM_BYTES (6 * 128 * 20 * 4)

template<int NC>
__global__ __launch_bounds__(256, 2) void gemm_tc3_kernel(
    const float* __restrict__ A, const float* __restrict__ W,
    const float* __restrict__ bias, float* __restrict__ C)
{
    extern __shared__ float sm[];

    const int tid  = threadIdx.x;
    const int lane = tid & 31;
    const int warp = tid >> 5;
    const int wm   = warp & 1;
    const int wn   = warp >> 1;
    const int g    = lane >> 2;
    const int t    = lane & 3;
    const long m0  = (long)blockIdx.y * 128;
    const int  n0  = blockIdx.x * 128;

    const int srow = tid >> 2;
    const int sf   = tid & 3;
    const float* gA = A + (m0 + srow) * 128 + sf * 4;
    const float* gW = W + ((size_t)n0 + srow) * 128 + sf * 4;
    const uint32_t sbase = (uint32_t)__cvta_generic_to_shared(sm);
    const uint32_t sA = sbase + (srow * 20 + sf * 4) * 4;
    const uint32_t sW = sA + 3 * 10240;
    const uint32_t BUFB  = 10240;
    const uint32_t ROW64 = 64 * 20 * 4;

    auto stage = [&](int kc, int buf) {
        const float* a = gA + kc * 16;
        const float* w = gW + kc * 16;
        CP_ASYNC16(sA + buf * BUFB,         a);
        CP_ASYNC16(sA + buf * BUFB + ROW64, a + 64 * 128);
        CP_ASYNC16(sW + buf * BUFB,         w);
        CP_ASYNC16(sW + buf * BUFB + ROW64, w + 64 * 128);
    };

    float acc[4][4][4] = {};

    stage(0, 0); CP_COMMIT();
    stage(1, 1); CP_COMMIT();

    #pragma unroll
    for (int kc = 0; kc < 8; kc++) {
        if (kc < 7) asm volatile("cp.async.wait_group 1;");
        else        asm volatile("cp.async.wait_group 0;");
        __syncthreads();
        if (kc < 6) { stage(kc + 2, (kc + 2) % 3); CP_COMMIT(); }

        const float* Ab = sm + (kc % 3) * 2560;
        const float* Wb = Ab + 3 * 2560;

        #pragma unroll
        for (int s = 0; s < 2; s++) {
            const int off = s * 8;
            uint32_t a[4][4];
            #pragma unroll
            for (int mt = 0; mt < 4; mt++) {
                int r = wm * 64 + mt * 16 + g;
                a[mt][0] = rna_bits(Ab[r * 20 + off + t]);
                a[mt][1] = rna_bits(Ab[(r + 8) * 20 + off + t]);
                a[mt][2] = rna_bits(Ab[r * 20 + off + t + 4]);
                a[mt][3] = rna_bits(Ab[(r + 8) * 20 + off + t + 4]);
            }
            #pragma unroll
            for (int nt = 0; nt < 4; nt++) {
                int n = wn * 32 + nt * 8 + g;
                uint32_t b0 = rna_bits(Wb[n * 20 + off + t]);
                uint32_t b1 = rna_bits(Wb[n * 20 + off + t + 4]);
                #pragma unroll
                for (int mt = 0; mt < 4; mt++)
                    mma_tf32(acc[mt][nt], a[mt], b0, b1);
            }
        }
    }

    #pragma unroll
    for (int nt = 0; nt < 4; nt++) {
        int col = n0 + wn * 32 + nt * 8 + 2 * t;
        float b0 = bias[col], b1 = bias[col + 1];
        #pragma unroll
        for (int mt = 0; mt < 4; mt++) {
            long r = m0 + wm * 64 + mt * 16 + g;
            *(float2*)&C[r * NC + col] =
                make_float2(acc[mt][nt][0] + b0, acc[mt][nt][1] + b1);
            *(float2*)&C[(r + 8) * NC + col] =
                make_float2(acc[mt][nt][2] + b0, acc[mt][nt][3] + b1);
        }
    }
}

// ---------------------------------------------------------------------------
// Precompute combined rel-pos bias + shift mask: g_comb[h][wm][i][j(pad 56)]
// ---------------------------------------------------------------------------
__global__ void precomp_bias_mask(const float* __restrict__ mask,
                                  const float* __restrict__ bias_table,
                                  const int* __restrict__ rel_index)
{
    const int wm = blockIdx.x;
    const int h  = blockIdx.y;
    float* dst = g_comb + ((size_t)h * 64 + wm) * 49 * 56;
    for (int q = threadIdx.x; q < 49 * 56; q += blockDim.x) {
        int i = q / 56, j = q - i * 56;
        dst[q] = (j < 49)
            ? bias_table[rel_index[i * 49 + j] * HEADS + h]
              + mask[(size_t)wm * (NWIN * NWIN) + i * 49 + j]
            : -1e30f;
    }
}

// ---------------------------------------------------------------------------
// Fused attention + output projection. Block = window b, 256 thr = 8 warps.
// Attention warps: (h = warp>>1, half = warp&1); each owns 32 rows of a head.
// Smem: one array S[64][388] holding qkv rows (Q|K|V = cols 0|128|256).
//   stride 388 == 4 (mod 32) -> A-fragment LDS (rows +g) conflict-free.
// Phase flow (4 block barriers):
//   cp.async qkv -> QK mma (+comb init) -> reg softmax -> P into dead Q/K
//   cols [h*56, h*56+56) -> PV mma -> O into cols 0..128 -> proj mma with
//   B-fragments LDG'd from proj_w (L1-resident) -> out.
// Pad rows 49..55 of K/V zeroed (pad S cols get comb=-1e30 -> P=0);
// pad output rows masked at store.
// ---------------------------------------------------------------------------
#define AP_SMEM_BYTES (64 * 388 * 4)   // 99328

__global__ __launch_bounds__(256, 2) void attn_proj_kernel(
    const float* __restrict__ qkv, const float* __restrict__ proj_w,
    const float* __restrict__ proj_b, float* __restrict__ outp)
{
    extern __shared__ float S[];       // [64][388]

    const int tid  = threadIdx.x;
    const int lane = tid & 31;
    const int warp = tid >> 5;
    const int g = lane >> 2, t = lane & 3;
    const int b = blockIdx.x;
    const int h    = warp >> 1;        // head 0..3
    const int half = warp & 1;         // row half 0..1
    const int r0   = half * 32 + g;
    const float scale = 0.17677669529663687f;   // 32^-0.5

    // ---- stage qkv slab: 49 rows x 384 floats, fully coalesced ----
    {
        const uint32_t sb = (uint32_t)__cvta_generic_to_shared(S);
        const float* src = qkv + ((size_t)b * 49) * 384;
        for (int q = tid; q < 49 * 96; q += 256) {
            const int i = q / 96, seg = q - i * 96;
            CP_ASYNC16(sb + (i * 388 + seg * 4) * 4, src + (size_t)i * 384 + seg * 4);
        }
        CP_COMMIT();
        // zero K/V pad rows 49..55 (cols 128..384)
        for (int q = tid; q < 7 * 256; q += 256) {
            const int i = 49 + (q >> 8), c2 = 128 + (q & 255);
            S[i * 388 + c2] = 0.f;
        }
    }

    // ---- init S accumulators from combined bias+mask (L2-hot) ----
    const float* comb = g_comb + ((size_t)h * 64 + (b & 63)) * 49 * 56;
    float c[2][7][4];
    #pragma unroll
    for (int mt = 0; mt < 2; mt++) {
        const int rA = r0 + mt * 16, rB = rA + 8;
        #pragma unroll
        for (int nt = 0; nt < 7; nt++) {
            const int col = nt * 8 + 2 * t;
            if (rA < 49) {
                float2 f = *(const float2*)&comb[rA * 56 + col];
                c[mt][nt][0] = f.x; c[mt][nt][1] = f.y;
            } else { c[mt][nt][0] = 0.f; c[mt][nt][1] = 0.f; }
            if (rB < 49) {
                float2 f = *(const float2*)&comb[rB * 56 + col];
                c[mt][nt][2] = f.x; c[mt][nt][3] = f.y;
            } else { c[mt][nt][2] = 0.f; c[mt][nt][3] = 0.f; }
        }
    }

    asm volatile("cp.async.wait_group 0;");
    __syncthreads();

    // ---- QK: S += (Q*scale) K^T ----
    #pragma unroll
    for (int s = 0; s < 4; s++) {
        const int off = s * 8;
        uint32_t a[2][4];
        #pragma unroll
        for (int mt = 0; mt < 2; mt++) {
            const int rA = r0 + mt * 16;
            a[mt][0] = rna_bits(S[rA * 388 + h * 32 + off + t] * scale);
            a[mt][1] = rna_bits(S[(rA + 8) * 388 + h * 32 + off + t] * scale);
            a[mt][2] = rna_bits(S[rA * 388 + h * 32 + off + t + 4] * scale);
            a[mt][3] = rna_bits(S[(rA + 8) * 388 + h * 32 + off + t + 4] * scale);
        }
        #pragma unroll
        for (int nt = 0; nt < 7; nt++) {
            const int kr = nt * 8 + g;
            uint32_t b0 = rna_bits(S[kr * 388 + 128 + h * 32 + off + t]);
            uint32_t b1 = rna_bits(S[kr * 388 + 128 + h * 32 + off + t + 4]);
            #pragma unroll
            for (int mt = 0; mt < 2; mt++)
                mma_tf32(c[mt][nt], a[mt], b0, b1);
        }
    }

    // ---- softmax in registers (4 row-groups per warp) ----
    float inv[2][2];
    #pragma unroll
    for (int mt = 0; mt < 2; mt++) {
        float mx0 = -1e30f, mx1 = -1e30f;
        #pragma unroll
        for (int nt = 0; nt < 7; nt++) {
            mx0 = fmaxf(mx0, fmaxf(c[mt][nt][0], c[mt][nt][1]));
            mx1 = fmaxf(mx1, fmaxf(c[mt][nt][2], c[mt][nt][3]));
        }
        mx0 = fmaxf(mx0, __shfl_xor_sync(0xffffffffu, mx0, 1));
        mx0 = fmaxf(mx0, __shfl_xor_sync(0xffffffffu, mx0, 2));
        mx1 = fmaxf(mx1, __shfl_xor_sync(0xffffffffu, mx1, 1));
        mx1 = fmaxf(mx1, __shfl_xor_sync(0xffffffffu, mx1, 2));
        float s0 = 0.f, s1 = 0.f;
        #pragma unroll
        for (int nt = 0; nt < 7; nt++) {
            c[mt][nt][0] = __expf(c[mt][nt][0] - mx0);
            c[mt][nt][1] = __expf(c[mt][nt][1] - mx0);
            c[mt][nt][2] = __expf(c[mt][nt][2] - mx1);
            c[mt][nt][3] = __expf(c[mt][nt][3] - mx1);
            s0 += c[mt][nt][0] + c[mt][nt][1];
            s1 += c[mt][nt][2] + c[mt][nt][3];
        }
        s0 += __shfl_xor_sync(0xffffffffu, s0, 1);
        s0 += __shfl_xor_sync(0xffffffffu, s0, 2);
        s1 += __shfl_xor_sync(0xffffffffu, s1, 1);
        s1 += __shfl_xor_sync(0xffffffffu, s1, 2);
        inv[mt][0] = 1.f / s0;
        inv[mt][1] = 1.f / s1;
    }

    // ---- write P into dead Q/K columns [h*56, h*56+56) ----
    __syncthreads();   // all QK reads of Q/K smem must be done
    #pragma unroll
    for (int mt = 0; mt < 2; mt++) {
        const int rA = r0 + mt * 16;
        #pragma unroll
        for (int nt = 0; nt < 7; nt++) {
            const int col = h * 56 + nt * 8 + 2 * t;
            S[rA * 388 + col]           = to_tf32(c[mt][nt][0] * inv[mt][0]);
            S[rA * 388 + col + 1]       = to_tf32(c[mt][nt][1] * inv[mt][0]);
            S[(rA + 8) * 388 + col]     = to_tf32(c[mt][nt][2] * inv[mt][1]);
            S[(rA + 8) * 388 + col + 1] = to_tf32(c[mt][nt][3] * inv[mt][1]);
        }
    }
    __syncwarp();       // own warp re-reads its own P rows

    // ---- PV: O = P V ----
    float o[2][4][4] = {};
    #pragma unroll
    for (int s = 0; s < 7; s++) {
        const int off = s * 8;
        uint32_t a[2][4];
        #pragma unroll
        for (int mt = 0; mt < 2; mt++) {
            const int rA = r0 + mt * 16;
            a[mt][0] = __float_as_uint(S[rA * 388 + h * 56 + off + t]);
            a[mt][1] = __float_as_uint(S[(rA + 8) * 388 + h * 56 + off + t]);
            a[mt][2] = __float_as_uint(S[rA * 388 + h * 56 + off + t + 4]);
            a[mt][3] = __float_as_uint(S[(rA + 8) * 388 + h * 56 + off + t + 4]);
        }
        #pragma unroll
        for (int nt = 0; nt < 4; nt++) {
            uint32_t b0 = rna_bits(S[(off + t) * 388 + 256 + h * 32 + nt * 8 + g]);
            uint32_t b1 = rna_bits(S[(off + t + 4) * 388 + 256 + h * 32 + nt * 8 + g]);
            #pragma unroll
            for (int mt = 0; mt < 2; mt++)
                mma_tf32(o[mt][nt], a[mt], b0, b1);
        }
    }

    // ---- write O (fp32) into cols 0..128 ----
    __syncthreads();   // all PV reads of P/V must be done
    #pragma unroll
    for (int mt = 0; mt < 2; mt++) {
        const int rA = r0 + mt * 16;
        #pragma unroll
        for (int nt = 0; nt < 4; nt++) {
            const int col = h * 32 + nt * 8 + 2 * t;
            S[rA * 388 + col]           = o[mt][nt][0];
            S[rA * 388 + col + 1]       = o[mt][nt][1];
            S[(rA + 8) * 388 + col]     = o[mt][nt][2];
            S[(rA + 8) * 388 + col + 1] = o[mt][nt][3];
        }
    }
    __syncthreads();

    // ---- proj: out = O @ proj_w^T + proj_b ----
    const int pm = warp & 1;           // 2 warps in m
    const int pn = warp >> 1;          // 4 warps in n
    float acc[2][4][4] = {};
    #pragma unroll 4
    for (int s = 0; s < 16; s++) {
        const int off = s * 8;
        uint32_t a[2][4];
        #pragma unroll
        for (int mt = 0; mt < 2; mt++) {
            const int rA = pm * 32 + mt * 16 + g;
            a[mt][0] = rna_bits(S[rA * 388 + off + t]);
            a[mt][1] = rna_bits(S[(rA + 8) * 388 + off + t]);
            a[mt][2] = rna_bits(S[rA * 388 + off + t + 4]);
            a[mt][3] = rna_bits(S[(rA + 8) * 388 + off + t + 4]);
        }
        #pragma unroll
        for (int nt = 0; nt < 4; nt++) {
            const int n = pn * 32 + nt * 8 + g;
            uint32_t b0 = rna_bits(proj_w[n * 128 + off + t]);
            uint32_t b1 = rna_bits(proj_w[n * 128 + off + t + 4]);
            #pragma unroll
            for (int mt = 0; mt < 2; mt++)
                mma_tf32(acc[mt][nt], a[mt], b0, b1);
        }
    }

    #pragma unroll
    for (int nt = 0; nt < 4; nt++) {
        const int col = pn * 32 + nt * 8 + 2 * t;
        const float b0 = proj_b[col], b1 = proj_b[col + 1];
        #pragma unroll
        for (int mt = 0; mt < 2; mt++) {
            const int r = pm * 32 + mt * 16 + g;
            if (r < 49)
                *(float2*)&outp[((size_t)b * 49 + r) * DIMC + col]
                    = make_float2(acc[mt][nt][0] + b0, acc[mt][nt][1] + b1);
            if (r + 8 < 49)
                *(float2*)&outp[((size_t)b * 49 + r + 8) * DIMC + col]
                    = make_float2(acc[mt][nt][2] + b0, acc[mt][nt][3] + b1);
        }
    }
}

// ---------------------------------------------------------------------------
extern "C" void kernel_launch(void* const* d_in, const int* in_sizes, int n_in,
                              void* d_out, int out_size)
{
    const float* x          = (const float*)d_in[0];
    const float* mask       = (const float*)d_in[1];
    const float* qkv_w      = (const float*)d_in[2];
    const float* qkv_b      = (const float*)d_in[3];
    const float* proj_w     = (const float*)d_in[4];
    const float* proj_b     = (const float*)d_in[5];
    const float* bias_table = (const float*)d_in[6];
    const int*   rel_index  = (const int*)d_in[7];
    float*       out        = (float*)d_out;

    float *qkvbuf = nullptr;
    cudaGetSymbolAddress((void**)&qkvbuf, g_qkv);

    cudaFuncSetAttribute(gemm_tc3_kernel<384>,
                         cudaFuncAttributeMaxDynamicSharedMemorySize, GEMM_SMEM_BYTES);
    cudaFuncSetAttribute(attn_proj_kernel,
                         cudaFuncAttributeMaxDynamicSharedMemorySize, AP_SMEM_BYTES);

    dim3 gp(64, 4);
    precomp_bias_mask<<<gp, 256>>>(mask, bias_table, rel_index);

    dim3 g1(384 / 128, M_TOTAL / 128);
    gemm_tc3_kernel<384><<<g1, 256, GEMM_SMEM_BYTES>>>(x, qkv_w, qkv_b, qkvbuf);

    attn_proj_kernel<<<NB, 256, AP_SMEM_BYTES>>>(qkvbuf, proj_w, proj_b, out);
}

// round 10
// speedup vs baseline: 1.1944x; 1.1944x over previous
#include <cuda_runtime.h>
#include <math.h>
#include <stdint.h>

// Problem constants
#define DIMC   128
#define NWIN   49
#define HEADS  4
#define HD     32
#define NB     4096
#define M_TOTAL (NB * NWIN)        // 200704 = 1568 * 128
#define M_TILES (M_TOTAL / 128)    // 1568

// Scratch (allocation-free rule: static device globals)
__device__ float g_qkv[(size_t)NB * NWIN * 384];   // [M, 384] : q|k|v per row
__device__ float g_att[(size_t)NB * NWIN * DIMC];  // [M, 128] : attention output
__device__ float g_comb[4 * 64 * 49 * 56];         // (bias+mask)*sqrt(hd), [h][wm][i][j]

__device__ __forceinline__ float to_tf32(float x) {
    float r;
    asm("cvt.rna.tf32.f32 %0, %1;" : "=f"(r) : "f"(x));
    return r;
}
// round-to-nearest tf32 as raw bits (tensor core truncates low 13 bits)
__device__ __forceinline__ uint32_t rna_bits(float x) {
    return __float_as_uint(x) + 0x1000u;
}

__device__ __forceinline__ void mma_tf32(float c[4], const uint32_t a[4],
                                         uint32_t b0, uint32_t b1) {
    asm volatile(
        "mma.sync.aligned.m16n8k8.row.col.f32.tf32.tf32.f32 "
        "{%0,%1,%2,%3}, {%4,%5,%6,%7}, {%8,%9}, {%0,%1,%2,%3};"
        : "+f"(c[0]), "+f"(c[1]), "+f"(c[2]), "+f"(c[3])
        : "r"(a[0]), "r"(a[1]), "r"(a[2]), "r"(a[3]), "r"(b0), "r"(b1));
}

#define CP_ASYNC16(dst, src) \
    asm volatile("cp.async.ca.shared.global [%0], [%1], 16;" :: "r"(dst), "l"(src))
#define CP_COMMIT() asm volatile("cp.async.commit_group;")

// ---------------------------------------------------------------------------
// tf32 GEMM v3 body (frozen round-5/8 winner):
// C[M][NC] = A[M][128] * W[NC][128]^T + bias.  128x128 tile, 8 warps,
// warp tile 64x32, 3-stage cp.async ring, stride-20 smem.
// ---------------------------------------------------------------------------
#define GEMM_SMEM_BYTES (6 * 128 * 20 * 4)

template<int NC>
__device__ __forceinline__ void gemm_tc3_body(
    const float* __restrict__ A, const float* __restrict__ W,
    const float* __restrict__ bias, float* __restrict__ C,
    float* sm, long m0, int n0)
{
    const int tid  = threadIdx.x;
    const int lane = tid & 31;
    const int warp = tid >> 5;
    const int wm   = warp & 1;
    const int wn   = warp >> 1;
    const int g    = lane >> 2;
    const int t    = lane & 3;

    const int srow = tid >> 2;
    const int sf   = tid & 3;
    const float* gA = A + (m0 + srow) * 128 + sf * 4;
    const float* gW = W + ((size_t)n0 + srow) * 128 + sf * 4;
    const uint32_t sbase = (uint32_t)__cvta_generic_to_shared(sm);
    const uint32_t sA = sbase + (srow * 20 + sf * 4) * 4;
    const uint32_t sW = sA + 3 * 10240;
    const uint32_t BUFB  = 10240;
    const uint32_t ROW64 = 64 * 20 * 4;

    auto stage = [&](int kc, int buf) {
        const float* a = gA + kc * 16;
        const float* w = gW + kc * 16;
        CP_ASYNC16(sA + buf * BUFB,         a);
        CP_ASYNC16(sA + buf * BUFB + ROW64, a + 64 * 128);
        CP_ASYNC16(sW + buf * BUFB,         w);
        CP_ASYNC16(sW + buf * BUFB + ROW64, w + 64 * 128);
    };

    float acc[4][4][4] = {};

    stage(0, 0); CP_COMMIT();
    stage(1, 1); CP_COMMIT();

    #pragma unroll
    for (int kc = 0; kc < 8; kc++) {
        if (kc < 7) asm volatile("cp.async.wait_group 1;");
        else        asm volatile("cp.async.wait_group 0;");
        __syncthreads();
        if (kc < 6) { stage(kc + 2, (kc + 2) % 3); CP_COMMIT(); }

        const float* Ab = sm + (kc % 3) * 2560;
        const float* Wb = Ab + 3 * 2560;

        #pragma unroll
        for (int s = 0; s < 2; s++) {
            const int off = s * 8;
            uint32_t a[4][4];
            #pragma unroll
            for (int mt = 0; mt < 4; mt++) {
                int r = wm * 64 + mt * 16 + g;
                a[mt][0] = rna_bits(Ab[r * 20 + off + t]);
                a[mt][1] = rna_bits(Ab[(r + 8) * 20 + off + t]);
                a[mt][2] = rna_bits(Ab[r * 20 + off + t + 4]);
                a[mt][3] = rna_bits(Ab[(r + 8) * 20 + off + t + 4]);
            }
            #pragma unroll
            for (int nt = 0; nt < 4; nt++) {
                int n = wn * 32 + nt * 8 + g;
                uint32_t b0 = rna_bits(Wb[n * 20 + off + t]);
                uint32_t b1 = rna_bits(Wb[n * 20 + off + t + 4]);
                #pragma unroll
                for (int mt = 0; mt < 4; mt++)
                    mma_tf32(acc[mt][nt], a[mt], b0, b1);
            }
        }
    }

    #pragma unroll
    for (int nt = 0; nt < 4; nt++) {
        int col = n0 + wn * 32 + nt * 8 + 2 * t;
        float b0 = bias[col], b1 = bias[col + 1];
        #pragma unroll
        for (int mt = 0; mt < 4; mt++) {
            long r = m0 + wm * 64 + mt * 16 + g;
            *(float2*)&C[r * NC + col] =
                make_float2(acc[mt][nt][0] + b0, acc[mt][nt][1] + b1);
            *(float2*)&C[(r + 8) * NC + col] =
                make_float2(acc[mt][nt][2] + b0, acc[mt][nt][3] + b1);
        }
    }
}

// GEMM3 (proj): plain gemm
template<int NC>
__global__ __launch_bounds__(256, 2) void gemm_tc3_kernel(
    const float* __restrict__ A, const float* __restrict__ W,
    const float* __restrict__ bias, float* __restrict__ C)
{
    extern __shared__ float sm[];
    gemm_tc3_body<NC>(A, W, bias, C, sm, (long)blockIdx.y * 128, blockIdx.x * 128);
}

// GEMM1 + fused precomp: extra grid rows (blockIdx.y >= M_TILES) build
// g_comb[h][wm][i][j(pad56)] = (bias + mask) * sqrt(hd); pad cols -1e30.
__global__ __launch_bounds__(256, 2) void gemm1_precomp_kernel(
    const float* __restrict__ A, const float* __restrict__ W,
    const float* __restrict__ bias, float* __restrict__ C,
    const float* __restrict__ mask, const float* __restrict__ bias_table,
    const int* __restrict__ rel_index)
{
    extern __shared__ float sm[];
    if (blockIdx.y >= M_TILES) {
        const int pid = (blockIdx.y - M_TILES) * 3 + blockIdx.x;
        if (pid >= 256) return;
        const int wm = pid & 63, h = pid >> 6;
        const float inv_scale = 5.656854249492381f;  // sqrt(32)
        float* dst = g_comb + ((size_t)h * 64 + wm) * 49 * 56;
        for (int q = threadIdx.x; q < 49 * 56; q += 256) {
            int i = q / 56, j = q - i * 56;
            dst[q] = (j < 49)
                ? (bias_table[rel_index[i * 49 + j] * HEADS + h]
                   + mask[(size_t)wm * (NWIN * NWIN) + i * 49 + j]) * inv_scale
                : -1e30f;
        }
        return;
    }
    gemm_tc3_body<384>(A, W, bias, C, sm, (long)blockIdx.y * 128, blockIdx.x * 128);
}

// ---------------------------------------------------------------------------
// Attention v4 (validated in round 6). Block = (window b, head h), 128 thr.
// cp.async staging of Q,K,V row-major (no transform). QK accumulators init
// from g_comb*sqrt(hd) (L2-hot); scale applied inside exp. Register softmax.
// P to smem natural layout; PV B-fragments read V row-major (conflict-free).
// tf32 RNA at fragment load. One __syncthreads + one __syncwarp.
// ---------------------------------------------------------------------------
__global__ __launch_bounds__(128) void attn_tc_kernel(
    const float* __restrict__ qkv, float* __restrict__ outp)
{
    __shared__ float Qs[64][40];   // rows 49..63 uninit (outputs masked)
    __shared__ float Ks[56][40];   // rows 49..55 zeroed
    __shared__ float Vs[56][40];   // rows 49..55 zeroed
    __shared__ float Ps[64][72];

    const int tid  = threadIdx.x;
    const int lane = tid & 31;
    const int warp = tid >> 5;
    const int g = lane >> 2, t = lane & 3;
    const int b = blockIdx.x >> 2, h = blockIdx.x & 3;
    const float scale = 0.17677669529663687f;   // 32^-0.5

    // ---- cp.async staging of Q, K, V (49 rows x 32 floats each) ----
    {
        const float* base = qkv + ((size_t)b * 49) * 384 + h * 32;
        const uint32_t sQ = (uint32_t)__cvta_generic_to_shared(&Qs[0][0]);
        const uint32_t sK = (uint32_t)__cvta_generic_to_shared(&Ks[0][0]);
        const uint32_t sV = (uint32_t)__cvta_generic_to_shared(&Vs[0][0]);
        for (int q = tid; q < 392; q += 128) {
            int i = q >> 3, seg = q & 7;
            CP_ASYNC16(sQ + (i * 40 + seg * 4) * 4, base + (size_t)i * 384 + seg * 4);
        }
        for (int q = tid; q < 392; q += 128) {
            int i = q >> 3, seg = q & 7;
            CP_ASYNC16(sK + (i * 40 + seg * 4) * 4, base + (size_t)i * 384 + 128 + seg * 4);
        }
        for (int q = tid; q < 392; q += 128) {
            int i = q >> 3, seg = q & 7;
            CP_ASYNC16(sV + (i * 40 + seg * 4) * 4, base + (size_t)i * 384 + 256 + seg * 4);
        }
        CP_COMMIT();
        // zero K/V pad rows (disjoint from cp.async targets)
        for (int q = tid; q < 7 * 40; q += 128) {
            int i = 49 + q / 40, c2 = q % 40;
            Ks[i][c2] = 0.f;
            Vs[i][c2] = 0.f;
        }
    }

    // ---- init S accumulators from comb*sqrt(hd) (overlaps with cp.async) ----
    const int r0 = warp * 16 + g;
    const float* comb = g_comb + ((size_t)h * 64 + (b & 63)) * 49 * 56;
    float c[7][4];
    #pragma unroll
    for (int nt = 0; nt < 7; nt++) {
        const int col = nt * 8 + 2 * t;
        if (r0 < 49) {
            float2 f = *(const float2*)&comb[r0 * 56 + col];
            c[nt][0] = f.x; c[nt][1] = f.y;
        } else { c[nt][0] = 0.f; c[nt][1] = 0.f; }
        if (r0 + 8 < 49) {
            float2 f = *(const float2*)&comb[(r0 + 8) * 56 + col];
            c[nt][2] = f.x; c[nt][3] = f.y;
        } else { c[nt][2] = 0.f; c[nt][3] = 0.f; }
    }

    asm volatile("cp.async.wait_group 0;");
    __syncthreads();

    // ---- S' = QK^T + comb*sqrt(hd) ----
    #pragma unroll
    for (int s = 0; s < 4; s++) {
        const int off = s * 8;
        uint32_t a[4];
        a[0] = rna_bits(Qs[r0][off + t]);
        a[1] = rna_bits(Qs[r0 + 8][off + t]);
        a[2] = rna_bits(Qs[r0][off + t + 4]);
        a[3] = rna_bits(Qs[r0 + 8][off + t + 4]);
        #pragma unroll
        for (int nt = 0; nt < 7; nt++) {
            uint32_t b0 = rna_bits(Ks[nt * 8 + g][off + t]);
            uint32_t b1 = rna_bits(Ks[nt * 8 + g][off + t + 4]);
            mma_tf32(c[nt], a, b0, b1);
        }
    }

    // ---- softmax(scale * S') in registers ----
    {
        float mx0 = -1e30f, mx1 = -1e30f;
        #pragma unroll
        for (int nt = 0; nt < 7; nt++) {
            mx0 = fmaxf(mx0, fmaxf(c[nt][0], c[nt][1]));
            mx1 = fmaxf(mx1, fmaxf(c[nt][2], c[nt][3]));
        }
        mx0 = fmaxf(mx0, __shfl_xor_sync(0xffffffffu, mx0, 1));
        mx0 = fmaxf(mx0, __shfl_xor_sync(0xffffffffu, mx0, 2));
        mx1 = fmaxf(mx1, __shfl_xor_sync(0xffffffffu, mx1, 1));
        mx1 = fmaxf(mx1, __shfl_xor_sync(0xffffffffu, mx1, 2));
        float s0 = 0.f, s1 = 0.f;
        #pragma unroll
        for (int nt = 0; nt < 7; nt++) {
            c[nt][0] = __expf((c[nt][0] - mx0) * scale);
            c[nt][1] = __expf((c[nt][1] - mx0) * scale);
            c[nt][2] = __expf((c[nt][2] - mx1) * scale);
            c[nt][3] = __expf((c[nt][3] - mx1) * scale);
            s0 += c[nt][0] + c[nt][1];
            s1 += c[nt][2] + c[nt][3];
        }
        s0 += __shfl_xor_sync(0xffffffffu, s0, 1);
        s0 += __shfl_xor_sync(0xffffffffu, s0, 2);
        s1 += __shfl_xor_sync(0xffffffffu, s1, 1);
        s1 += __shfl_xor_sync(0xffffffffu, s1, 2);
        const float i0 = 1.f / s0, i1 = 1.f / s1;

        #pragma unroll
        for (int nt = 0; nt < 7; nt++) {
            const int col = nt * 8 + 2 * t;
            *(float2*)&Ps[r0][col] =
                make_float2(to_tf32(c[nt][0] * i0), to_tf32(c[nt][1] * i0));
            *(float2*)&Ps[r0 + 8][col] =
                make_float2(to_tf32(c[nt][2] * i1), to_tf32(c[nt][3] * i1));
        }
    }
    __syncwarp();

    // ---- O = P V ----
    float o[4][4];
    #pragma unroll
    for (int nt = 0; nt < 4; nt++)
        #pragma unroll
        for (int e = 0; e < 4; e++) o[nt][e] = 0.f;

    #pragma unroll
    for (int s = 0; s < 7; s++) {
        const int off = s * 8;
        uint32_t a[4];
        a[0] = __float_as_uint(Ps[r0][off + t]);
        a[1] = __float_as_uint(Ps[r0 + 8][off + t]);
        a[2] = __float_as_uint(Ps[r0][off + t + 4]);
        a[3] = __float_as_uint(Ps[r0 + 8][off + t + 4]);
        #pragma unroll
        for (int nt = 0; nt < 4; nt++) {
            uint32_t b0 = rna_bits(Vs[off + t][nt * 8 + g]);
            uint32_t b1 = rna_bits(Vs[off + t + 4][nt * 8 + g]);
            mma_tf32(o[nt], a, b0, b1);
        }
    }

    #pragma unroll
    for (int nt = 0; nt < 4; nt++) {
        const int d = nt * 8 + 2 * t;
        if (r0 < 49)
            *(float2*)&outp[((size_t)b * 49 + r0) * DIMC + h * HD + d]
                = make_float2(o[nt][0], o[nt][1]);
        if (r0 + 8 < 49)
            *(float2*)&outp[((size_t)b * 49 + r0 + 8) * DIMC + h * HD + d]
                = make_float2(o[nt][2], o[nt][3]);
    }
}

// ---------------------------------------------------------------------------
extern "C" void kernel_launch(void* const* d_in, const int* in_sizes, int n_in,
                              void* d_out, int out_size)
{
    const float* x          = (const float*)d_in[0];
    const float* mask       = (const float*)d_in[1];
    const float* qkv_w      = (const float*)d_in[2];
    const float* qkv_b      = (const float*)d_in[3];
    const float* proj_w     = (const float*)d_in[4];
    const float* proj_b     = (const float*)d_in[5];
    const float* bias_table = (const float*)d_in[6];
    const int*   rel_index  = (const int*)d_in[7];
    float*       out        = (float*)d_out;

    float *qkvbuf = nullptr, *attbuf = nullptr;
    cudaGetSymbolAddress((void**)&qkvbuf, g_qkv);
    cudaGetSymbolAddress((void**)&attbuf, g_att);

    cudaFuncSetAttribute(gemm1_precomp_kernel,
                         cudaFuncAttributeMaxDynamicSharedMemorySize, GEMM_SMEM_BYTES);
    cudaFuncSetAttribute(gemm_tc3_kernel<DIMC>,
                         cudaFuncAttributeMaxDynamicSharedMemorySize, GEMM_SMEM_BYTES);

    // GEMM1 with precomp folded in as extra grid rows (86 rows x 3 = 258 blocks)
    dim3 g1(384 / 128, M_TILES + 86);
    gemm1_precomp_kernel<<<g1, 256, GEMM_SMEM_BYTES>>>(
        x, qkv_w, qkv_b, qkvbuf, mask, bias_table, rel_index);

    attn_tc_kernel<<<NB * HEADS, 128>>>(qkvbuf, attbuf);

    dim3 g3(DIMC / 128, M_TILES);
    gemm_tc3_kernel<DIMC><<<g3, 256, GEMM_SMEM_BYTES>>>(attbuf, proj_w, proj_b, out);
}